// round 7
// baseline (speedup 1.0000x reference)
#include <cuda_runtime.h>
#include <cstdint>
#include <cstddef>

// ---------------- problem constants ----------------
#define T_TOKENS   8192
#define DM         2048
#define DH         8192
#define NEXP       8
#define CAP        2560
#define NITEMS     (T_TOKENS*2)

// ---------------- device scratch (static) ----------
__device__ float g_buf [(size_t)NEXP*CAP*DM];     // dispatched x (tf32-rounded)
__device__ float g_h   [(size_t)NEXP*CAP*DH];     // hidden (tf32-rounded)
__device__ float g_oute[(size_t)NEXP*CAP*DM];     // expert outputs (fp32)
__device__ int   g_item_e  [NITEMS];
__device__ float g_item_w  [NITEMS];
__device__ int   g_item_pos[NITEMS];
__device__ int   g_count   [NEXP];

// ---------------- helpers --------------------------
__device__ __forceinline__ float tf32rn(float x) {
    uint32_t u; asm("cvt.rna.tf32.f32 %0, %1;" : "=r"(u) : "f"(x));
    return __uint_as_float(u);
}
__device__ __forceinline__ uint32_t tf32u(float x) {
    uint32_t u; asm("cvt.rna.tf32.f32 %0, %1;" : "=r"(u) : "f"(x));
    return u;
}
__device__ __forceinline__ uint32_t smem_u32(const void* p) {
    uint32_t a;
    asm("{ .reg .u64 t; cvta.to.shared.u64 t, %1; cvt.u32.u64 %0, t; }" : "=r"(a) : "l"(p));
    return a;
}
__device__ __forceinline__ void cpasync16(uint32_t dst, const void* src) {
    asm volatile("cp.async.cg.shared.global [%0], [%1], 16;" :: "r"(dst), "l"(src));
}
__device__ __forceinline__ void cp_commit() {
    asm volatile("cp.async.commit_group;" ::: "memory");
}
__device__ __forceinline__ void cp_wait1() {
    asm volatile("cp.async.wait_group 1;" ::: "memory");
}
__device__ __forceinline__ void cp_wait0() {
    asm volatile("cp.async.wait_group 0;" ::: "memory");
}
__device__ __forceinline__ void mma_tf32(float* c, const uint32_t* a, const uint32_t* b) {
    asm volatile(
        "mma.sync.aligned.m16n8k8.row.col.f32.tf32.tf32.f32 "
        "{%0,%1,%2,%3}, {%4,%5,%6,%7}, {%8,%9}, {%0,%1,%2,%3};"
        : "+f"(c[0]), "+f"(c[1]), "+f"(c[2]), "+f"(c[3])
        : "r"(a[0]), "r"(a[1]), "r"(a[2]), "r"(a[3]), "r"(b[0]), "r"(b[1]));
}

// ---------------- 1) gating -------------------------
__global__ void gating_kernel(const float* __restrict__ x,
                              const float* __restrict__ gw) {
    int t = blockIdx.x;
    const float* xt = x + (size_t)t * DM;
    float acc[NEXP];
#pragma unroll
    for (int e = 0; e < NEXP; e++) acc[e] = 0.f;
    for (int d = threadIdx.x; d < DM; d += blockDim.x) {
        float xv = xt[d];
        const float* g = gw + (size_t)d * NEXP;
#pragma unroll
        for (int e = 0; e < NEXP; e++) acc[e] += xv * g[e];
    }
    __shared__ float red[NEXP][128];
#pragma unroll
    for (int e = 0; e < NEXP; e++) red[e][threadIdx.x] = acc[e];
    __syncthreads();
    for (int s = 64; s > 0; s >>= 1) {
        if (threadIdx.x < s) {
#pragma unroll
            for (int e = 0; e < NEXP; e++)
                red[e][threadIdx.x] += red[e][threadIdx.x + s];
        }
        __syncthreads();
    }
    if (threadIdx.x == 0) {
        float l[NEXP];
#pragma unroll
        for (int e = 0; e < NEXP; e++) l[e] = red[e][0];
        float m = l[0];
#pragma unroll
        for (int e = 1; e < NEXP; e++) m = fmaxf(m, l[e]);
        float p[NEXP]; float Z = 0.f;
#pragma unroll
        for (int e = 0; e < NEXP; e++) { p[e] = __expf(l[e] - m); Z += p[e]; }
        int i0 = 0;
#pragma unroll
        for (int e = 1; e < NEXP; e++) if (p[e] > p[i0]) i0 = e;
        int i1 = (i0 == 0) ? 1 : 0;
#pragma unroll
        for (int e = 0; e < NEXP; e++) if (e != i0 && p[e] > p[i1]) i1 = e;
        float w0 = p[i0] / Z, w1 = p[i1] / Z;
        float s = w0 + w1 + 1e-8f;
        g_item_e[2*t]   = i0;  g_item_e[2*t+1] = i1;
        g_item_w[2*t]   = w0 / s;
        g_item_w[2*t+1] = w1 / s;
    }
}

// ---------------- 2) serial positions ---------------
__global__ void position_kernel() {
    __shared__ int cnt[256][NEXP];
    int tid = threadIdx.x;
    int base = tid * (NITEMS / 256);
    int local[NEXP];
#pragma unroll
    for (int e = 0; e < NEXP; e++) local[e] = 0;
    for (int i = 0; i < NITEMS/256; i++) local[g_item_e[base + i]]++;
#pragma unroll
    for (int e = 0; e < NEXP; e++) cnt[tid][e] = local[e];
    __syncthreads();
    if (tid < NEXP) {
        int run = 0;
        for (int j = 0; j < 256; j++) { int c = cnt[j][tid]; cnt[j][tid] = run; run += c; }
        g_count[tid] = run < CAP ? run : CAP;
    }
    __syncthreads();
    int run[NEXP];
#pragma unroll
    for (int e = 0; e < NEXP; e++) run[e] = cnt[tid][e];
    for (int i = 0; i < NITEMS/256; i++) {
        int e = g_item_e[base + i];
        g_item_pos[base + i] = run[e]++;
    }
}

// ---------------- 3) dispatch (tf32 round) ----------
__global__ void dispatch_kernel(const float* __restrict__ x) {
    int i = blockIdx.x;
    int pos = g_item_pos[i];
    if (pos >= CAP) return;
    int e = g_item_e[i];
    int t = i >> 1;
    const float4* src = (const float4*)(x + (size_t)t * DM);
    float4* dst = (float4*)(g_buf + ((size_t)e * CAP + pos) * DM);
    for (int j = threadIdx.x; j < DM/4; j += blockDim.x) {
        float4 v = src[j];
        v.x = tf32rn(v.x); v.y = tf32rn(v.y); v.z = tf32rn(v.z); v.w = tf32rn(v.w);
        dst[j] = v;
    }
}

// ---------------- 4) HMMA TF32 GEMM -----------------
// C[e] = act(A[e] @ B[e] + bias[e]);  A:[CAP][K] (tf32 values), B:[K][N] fp32
// CTA 128x128x32, 256 threads, 8 warps of 64x32, 3-stage cp.async pipeline.
// k-slot relabeling (slot tg -> logical 2tg, slot tg+4 -> logical 2tg+1)
// makes A fragments contiguous -> LDS.64.
#define GSMEM (3*(128*32 + 32*128)*4)   // 96 KB

template<bool RELU, bool CVT>
__global__ void __launch_bounds__(256, 2)
moe_gemm(const float* __restrict__ Aall, const float* __restrict__ Ball,
         const float* __restrict__ biasall, float* __restrict__ Call,
         int N, int K) {
    int e  = blockIdx.z;
    int bm = blockIdx.y * 128;
    int bn = blockIdx.x * 128;
    if (bm >= g_count[e]) return;

    const float* A = Aall + (size_t)e * CAP * K + (size_t)bm * K;
    const float* B = Ball + (size_t)e * K * N + bn;
    const float* bias = biasall + (size_t)e * N + bn;
    float* C = Call + (size_t)e * CAP * N;

    extern __shared__ float smem[];
    uint32_t sbase = smem_u32(smem);

    int tid = threadIdx.x;
    int wid = tid >> 5, lane = tid & 31;
    int gr = lane >> 2, tg = lane & 3;
    int wm = (wid & 1) * 64, wn = (wid >> 1) * 32;   // 2x4 warp grid, 64x32 tiles

    // staging assignments (256 threads)
    int a_r = tid >> 1;             // A row 0..127
    int a_h = tid & 1;              // chunk half (4 chunks each)
    int b_r = tid >> 3;             // B row 0..31
    int b_c = tid & 7;              // B chunk phase (4 chunks each)
    const float* aRow = A + (size_t)a_r * K;
    const float* bRow = B + (size_t)b_r * N;

    float acc[4][4][4];
#pragma unroll
    for (int mi = 0; mi < 4; mi++)
#pragma unroll
        for (int ni = 0; ni < 4; ni++)
#pragma unroll
            for (int r = 0; r < 4; r++) acc[mi][ni][r] = 0.f;

    int NB = K / 32;

    // stage loader: buffer buf (0..2), k offset kbig*32
    auto stage = [&](int buf, int kbig) {
        uint32_t aDst = sbase + buf * 16384 + a_r * 128;          // bytes
        const float* aSrc = aRow + kbig * 32;
#pragma unroll
        for (int j = 0; j < 4; j++) {
            int c = a_h * 4 + j;
            cpasync16(aDst + (((uint32_t)(c ^ (a_r & 7))) << 4), aSrc + c * 4);
        }
        uint32_t bDst = sbase + 49152 + buf * 16384 + b_r * 512;
        const float* bSrc = bRow + (size_t)kbig * 32 * N;
#pragma unroll
        for (int j = 0; j < 4; j++) {
            int c = b_c + j * 8;
            cpasync16(bDst + (((uint32_t)(c ^ ((b_r & 3) << 1))) << 4), bSrc + c * 4);
        }
    };

    // prologue: stages 0 and 1 in flight
    stage(0, 0); cp_commit();
    stage(1, 1); cp_commit();

    int buf = 0;
    for (int big = 0; big < NB; big++) {
        if (big + 2 < NB) cp_wait1(); else cp_wait0();
        __syncthreads();   // single barrier per iteration

        if (big + 2 < NB) {
            int nbuf = buf + 2; if (nbuf >= 3) nbuf -= 3;
            stage(nbuf, big + 2);
            cp_commit();
        }

        const char*  sAb = (const char*)(smem + buf * 4096);
        const float* sB  = smem + 12288 + buf * 4096;
#pragma unroll
        for (int kk = 0; kk < 32; kk += 8) {
            // A fragments: k-slot tg = logical kk+2tg, slot tg+4 = logical kk+2tg+1
            int ob = (kk + 2 * tg) * 4;              // byte offset in 128B row
            uint32_t grp = (uint32_t)ob >> 4, within = (uint32_t)ob & 15;
            uint32_t a[4][4];
#pragma unroll
            for (int mi = 0; mi < 4; mi++) {
                int m0 = wm + mi * 16 + gr;
                uint32_t sw = (uint32_t)((grp ^ (m0 & 7)) << 4) + within;
                float2 v0 = *(const float2*)(sAb + m0 * 128 + sw);
                float2 v1 = *(const float2*)(sAb + (m0 + 8) * 128 + sw);
                a[mi][0] = __float_as_uint(v0.x);
                a[mi][1] = __float_as_uint(v1.x);
                a[mi][2] = __float_as_uint(v0.y);
                a[mi][3] = __float_as_uint(v1.y);
            }
            // B fragments: rows kk+2tg (slot tg) and kk+2tg+1 (slot tg+4)
            int kr0 = kk + 2 * tg, kr1 = kr0 + 1;
            int sw0 = (kr0 & 3) << 3, sw1 = (kr1 & 3) << 3;
            uint32_t b[4][2];
#pragma unroll
            for (int ni = 0; ni < 4; ni++) {
                int n0 = wn + ni * 8 + gr;
                b[ni][0] = tf32u(sB[kr0 * 128 + (n0 ^ sw0)]);
                b[ni][1] = tf32u(sB[kr1 * 128 + (n0 ^ sw1)]);
            }
#pragma unroll
            for (int mi = 0; mi < 4; mi++)
#pragma unroll
                for (int ni = 0; ni < 4; ni++)
                    mma_tf32(acc[mi][ni], a[mi], b[ni]);
        }

        buf++; if (buf >= 3) buf = 0;
    }

    // epilogue
#pragma unroll
    for (int mi = 0; mi < 4; mi++) {
        int row0 = bm + wm + mi * 16 + gr;
        int row1 = row0 + 8;
#pragma unroll
        for (int ni = 0; ni < 4; ni++) {
            int col = wn + ni * 8 + 2 * tg;
            float2 b2 = *(const float2*)(bias + col);
            float v0 = acc[mi][ni][0] + b2.x;
            float v1 = acc[mi][ni][1] + b2.y;
            float v2 = acc[mi][ni][2] + b2.x;
            float v3 = acc[mi][ni][3] + b2.y;
            if (RELU) {
                v0 = fmaxf(v0, 0.f); v1 = fmaxf(v1, 0.f);
                v2 = fmaxf(v2, 0.f); v3 = fmaxf(v3, 0.f);
            }
            if (CVT) {
                v0 = tf32rn(v0); v1 = tf32rn(v1);
                v2 = tf32rn(v2); v3 = tf32rn(v3);
            }
            float2 o0 = {v0, v1}, o1 = {v2, v3};
            *(float2*)(C + (size_t)row0 * N + bn + col) = o0;
            *(float2*)(C + (size_t)row1 * N + bn + col) = o1;
        }
    }
}

// ---------------- 5) combine ------------------------
__global__ void combine_kernel(float* __restrict__ out) {
    int t = blockIdx.x;
    int i0 = 2 * t, i1 = 2 * t + 1;
    int e0 = g_item_e[i0], e1 = g_item_e[i1];
    int p0 = g_item_pos[i0], p1 = g_item_pos[i1];
    float w0 = (p0 < CAP) ? g_item_w[i0] : 0.f;
    float w1 = (p1 < CAP) ? g_item_w[i1] : 0.f;
    if (p0 >= CAP) p0 = CAP - 1;
    if (p1 >= CAP) p1 = CAP - 1;
    const float4* s0 = (const float4*)(g_oute + ((size_t)e0 * CAP + p0) * DM);
    const float4* s1 = (const float4*)(g_oute + ((size_t)e1 * CAP + p1) * DM);
    float4* dst = (float4*)(out + (size_t)t * DM);
    for (int j = threadIdx.x; j < DM/4; j += blockDim.x) {
        float4 a = s0[j], b = s1[j];
        float4 r;
        r.x = w0 * a.x + w1 * b.x;
        r.y = w0 * a.y + w1 * b.y;
        r.z = w0 * a.z + w1 * b.z;
        r.w = w0 * a.w + w1 * b.w;
        dst[j] = r;
    }
}

// ---------------- launcher --------------------------
extern "C" void kernel_launch(void* const* d_in, const int* in_sizes, int n_in,
                              void* d_out, int out_size) {
    const float* x  = (const float*)d_in[0];
    const float* gw = (const float*)d_in[1];
    const float* w1 = (const float*)d_in[2];
    const float* b1 = (const float*)d_in[3];
    const float* w2 = (const float*)d_in[4];
    const float* b2 = (const float*)d_in[5];
    float* out = (float*)d_out;

    void *pbuf, *ph, *poute;
    cudaGetSymbolAddress(&pbuf,  g_buf);
    cudaGetSymbolAddress(&ph,    g_h);
    cudaGetSymbolAddress(&poute, g_oute);

    cudaFuncSetAttribute(moe_gemm<true,  true >, cudaFuncAttributeMaxDynamicSharedMemorySize, GSMEM);
    cudaFuncSetAttribute(moe_gemm<false, false>, cudaFuncAttributeMaxDynamicSharedMemorySize, GSMEM);

    gating_kernel<<<T_TOKENS, 128>>>(x, gw);
    position_kernel<<<1, 256>>>();
    dispatch_kernel<<<NITEMS, 128>>>(x);

    // h = relu(buf @ w1 + b1): N=DH, K=DM
    moe_gemm<true,  true ><<<dim3(DH/128, CAP/128, NEXP), 256, GSMEM>>>(
        (const float*)pbuf, w1, b1, (float*)ph, DH, DM);
    // oute = h @ w2 + b2: N=DM, K=DH
    moe_gemm<false, false><<<dim3(DM/128, CAP/128, NEXP), 256, GSMEM>>>(
        (const float*)ph, w2, b2, (float*)poute, DM, DH);

    combine_kernel<<<T_TOKENS, 128>>>(out);
}

// round 8
// speedup vs baseline: 1.2061x; 1.2061x over previous
#include <cuda_runtime.h>
#include <cstdint>
#include <cstddef>

// ---------------- problem constants ----------------
#define T_TOKENS   8192
#define DM         2048
#define DH         8192
#define NEXP       8
#define CAP        2560
#define NITEMS     (T_TOKENS*2)

// ---------------- device scratch (static) ----------
__device__ float g_buf [(size_t)NEXP*CAP*DM];     // dispatched x (tf32-rounded)
__device__ float g_h   [(size_t)NEXP*CAP*DH];     // hidden (tf32-rounded)
__device__ float g_oute[(size_t)NEXP*CAP*DM];     // expert outputs (fp32)
__device__ float g_w1r [(size_t)NEXP*(size_t)DM*DH]; // w1 tf32-rounded (same layout)
__device__ float g_w2r [(size_t)NEXP*(size_t)DM*DH]; // w2 tf32-rounded (same layout)
__device__ int   g_item_e  [NITEMS];
__device__ float g_item_w  [NITEMS];
__device__ int   g_item_pos[NITEMS];
__device__ int   g_count   [NEXP];

// ---------------- helpers --------------------------
__device__ __forceinline__ float tf32rn(float x) {
    uint32_t u; asm("cvt.rna.tf32.f32 %0, %1;" : "=r"(u) : "f"(x));
    return __uint_as_float(u);
}
__device__ __forceinline__ uint32_t smem_u32(const void* p) {
    uint32_t a;
    asm("{ .reg .u64 t; cvta.to.shared.u64 t, %1; cvt.u32.u64 %0, t; }" : "=r"(a) : "l"(p));
    return a;
}
__device__ __forceinline__ void cpasync16(uint32_t dst, const void* src) {
    asm volatile("cp.async.cg.shared.global [%0], [%1], 16;" :: "r"(dst), "l"(src));
}
__device__ __forceinline__ void cp_commit() {
    asm volatile("cp.async.commit_group;" ::: "memory");
}
__device__ __forceinline__ void cp_wait1() {
    asm volatile("cp.async.wait_group 1;" ::: "memory");
}
__device__ __forceinline__ void cp_wait0() {
    asm volatile("cp.async.wait_group 0;" ::: "memory");
}
__device__ __forceinline__ void mma_tf32(float* c, const uint32_t* a, const uint32_t* b) {
    asm volatile(
        "mma.sync.aligned.m16n8k8.row.col.f32.tf32.tf32.f32 "
        "{%0,%1,%2,%3}, {%4,%5,%6,%7}, {%8,%9}, {%0,%1,%2,%3};"
        : "+f"(c[0]), "+f"(c[1]), "+f"(c[2]), "+f"(c[3])
        : "r"(a[0]), "r"(a[1]), "r"(a[2]), "r"(a[3]), "r"(b[0]), "r"(b[1]));
}

// ---------------- 1) gating -------------------------
__global__ void gating_kernel(const float* __restrict__ x,
                              const float* __restrict__ gw) {
    int t = blockIdx.x;
    const float* xt = x + (size_t)t * DM;
    float acc[NEXP];
#pragma unroll
    for (int e = 0; e < NEXP; e++) acc[e] = 0.f;
    for (int d = threadIdx.x; d < DM; d += blockDim.x) {
        float xv = xt[d];
        const float* g = gw + (size_t)d * NEXP;
#pragma unroll
        for (int e = 0; e < NEXP; e++) acc[e] += xv * g[e];
    }
    __shared__ float red[NEXP][128];
#pragma unroll
    for (int e = 0; e < NEXP; e++) red[e][threadIdx.x] = acc[e];
    __syncthreads();
    for (int s = 64; s > 0; s >>= 1) {
        if (threadIdx.x < s) {
#pragma unroll
            for (int e = 0; e < NEXP; e++)
                red[e][threadIdx.x] += red[e][threadIdx.x + s];
        }
        __syncthreads();
    }
    if (threadIdx.x == 0) {
        float l[NEXP];
#pragma unroll
        for (int e = 0; e < NEXP; e++) l[e] = red[e][0];
        float m = l[0];
#pragma unroll
        for (int e = 1; e < NEXP; e++) m = fmaxf(m, l[e]);
        float p[NEXP]; float Z = 0.f;
#pragma unroll
        for (int e = 0; e < NEXP; e++) { p[e] = __expf(l[e] - m); Z += p[e]; }
        int i0 = 0;
#pragma unroll
        for (int e = 1; e < NEXP; e++) if (p[e] > p[i0]) i0 = e;
        int i1 = (i0 == 0) ? 1 : 0;
#pragma unroll
        for (int e = 0; e < NEXP; e++) if (e != i0 && p[e] > p[i1]) i1 = e;
        float w0 = p[i0] / Z, w1 = p[i1] / Z;
        float s = w0 + w1 + 1e-8f;
        g_item_e[2*t]   = i0;  g_item_e[2*t+1] = i1;
        g_item_w[2*t]   = w0 / s;
        g_item_w[2*t+1] = w1 / s;
    }
}

// ---------------- 2) serial positions ---------------
__global__ void position_kernel() {
    __shared__ int cnt[256][NEXP];
    int tid = threadIdx.x;
    int base = tid * (NITEMS / 256);
    int local[NEXP];
#pragma unroll
    for (int e = 0; e < NEXP; e++) local[e] = 0;
    for (int i = 0; i < NITEMS/256; i++) local[g_item_e[base + i]]++;
#pragma unroll
    for (int e = 0; e < NEXP; e++) cnt[tid][e] = local[e];
    __syncthreads();
    if (tid < NEXP) {
        int run = 0;
        for (int j = 0; j < 256; j++) { int c = cnt[j][tid]; cnt[j][tid] = run; run += c; }
        g_count[tid] = run < CAP ? run : CAP;
    }
    __syncthreads();
    int run[NEXP];
#pragma unroll
    for (int e = 0; e < NEXP; e++) run[e] = cnt[tid][e];
    for (int i = 0; i < NITEMS/256; i++) {
        int e = g_item_e[base + i];
        g_item_pos[base + i] = run[e]++;
    }
}

// ---------------- 3) dispatch (tf32 round) ----------
__global__ void dispatch_kernel(const float* __restrict__ x) {
    int i = blockIdx.x;
    int pos = g_item_pos[i];
    if (pos >= CAP) return;
    int e = g_item_e[i];
    int t = i >> 1;
    const float4* src = (const float4*)(x + (size_t)t * DM);
    float4* dst = (float4*)(g_buf + ((size_t)e * CAP + pos) * DM);
    for (int j = threadIdx.x; j < DM/4; j += blockDim.x) {
        float4 v = src[j];
        v.x = tf32rn(v.x); v.y = tf32rn(v.y); v.z = tf32rn(v.z); v.w = tf32rn(v.w);
        dst[j] = v;
    }
}

// ---------------- 3b) weight tf32 pre-round (no transpose)
__global__ void weight_cvt_kernel(const float* __restrict__ in,
                                  float* __restrict__ out, size_t n4) {
    size_t i = (size_t)blockIdx.x * blockDim.x + threadIdx.x;
    size_t stride = (size_t)gridDim.x * blockDim.x;
    const float4* I = (const float4*)in;
    float4* O = (float4*)out;
    for (; i < n4; i += stride) {
        float4 v = I[i];
        v.x = tf32rn(v.x); v.y = tf32rn(v.y); v.z = tf32rn(v.z); v.w = tf32rn(v.w);
        O[i] = v;
    }
}

// ---------------- 4) HMMA TF32 GEMM -----------------
// C[e] = act(A[e] @ B[e] + bias[e]);  A:[CAP][K], B:[K][N] (both tf32-valued fp32)
// CTA 128x128x32, 256 threads, 8 warps of 64x32, 3-stage cp.async pipeline,
// ONE __syncthreads per K-iteration.  2 CTAs/SM -> 4 warps/SMSP.
#define GSMEM (3*(128*32 + 32*128)*4)   // 96 KB

template<bool RELU, bool CVT>
__global__ void __launch_bounds__(256, 2)
moe_gemm(const float* __restrict__ Aall, const float* __restrict__ Ball,
         const float* __restrict__ biasall, float* __restrict__ Call,
         int N, int K) {
    int e  = blockIdx.z;
    int bm = blockIdx.y * 128;
    int bn = blockIdx.x * 128;
    if (bm >= g_count[e]) return;

    const float* A = Aall + (size_t)e * CAP * K + (size_t)bm * K;
    const float* B = Ball + (size_t)e * K * N + bn;
    const float* bias = biasall + (size_t)e * N + bn;
    float* C = Call + (size_t)e * CAP * N;

    extern __shared__ float smem[];
    uint32_t sbase = smem_u32(smem);

    int tid = threadIdx.x;
    int wid = tid >> 5, lane = tid & 31;
    int gr = lane >> 2, tg = lane & 3;
    int wm = (wid & 1) * 64, wn = (wid >> 1) * 32;   // 2x4 warp grid, 64x32 tiles

    // staging assignments (256 threads)
    int a_r = tid >> 1;             // A row 0..127
    int a_h = tid & 1;              // chunk half (4 chunks each)
    int b_r = tid >> 3;             // B row 0..31
    int b_c = tid & 7;              // B chunk phase (4 chunks each)
    const float* aRow = A + (size_t)a_r * K;
    const float* bRow = B + (size_t)b_r * N;

    float acc[4][4][4];
#pragma unroll
    for (int mi = 0; mi < 4; mi++)
#pragma unroll
        for (int ni = 0; ni < 4; ni++)
#pragma unroll
            for (int r = 0; r < 4; r++) acc[mi][ni][r] = 0.f;

    int NB = K / 32;

    // stage loader: buffer buf (0..2), k offset kbig*32
    auto stage = [&](int buf, int kbig) {
        uint32_t aDst = sbase + buf * 16384 + a_r * 128;          // bytes
        const float* aSrc = aRow + kbig * 32;
#pragma unroll
        for (int j = 0; j < 4; j++) {
            int c = a_h * 4 + j;
            cpasync16(aDst + (((uint32_t)(c ^ (a_r & 7))) << 4), aSrc + c * 4);
        }
        uint32_t bDst = sbase + 49152 + buf * 16384 + b_r * 512;
        const float* bSrc = bRow + (size_t)kbig * 32 * N;
#pragma unroll
        for (int j = 0; j < 4; j++) {
            int c = b_c + j * 8;
            cpasync16(bDst + (((uint32_t)(c ^ ((b_r & 3) << 1))) << 4), bSrc + c * 4);
        }
    };

    // prologue: stages 0 and 1 in flight
    stage(0, 0); cp_commit();
    stage(1, 1); cp_commit();

    int buf = 0;
    for (int big = 0; big < NB; big++) {
        if (big + 2 < NB) cp_wait1(); else cp_wait0();
        __syncthreads();   // single barrier per iteration

        if (big + 2 < NB) {
            int nbuf = buf + 2; if (nbuf >= 3) nbuf -= 3;
            stage(nbuf, big + 2);
            cp_commit();
        }

        const float* sA = smem + buf * 4096;
        const float* sB = smem + 12288 + buf * 4096;
#pragma unroll
        for (int kk = 0; kk < 32; kk += 8) {
            uint32_t a[4][4];
#pragma unroll
            for (int mi = 0; mi < 4; mi++) {
                int m0 = wm + mi * 16 + gr;
                int k0 = (kk + tg) ^ (gr << 2);
                int k1 = (kk + tg + 4) ^ (gr << 2);
                a[mi][0] = __float_as_uint(sA[m0 * 32 + k0]);
                a[mi][1] = __float_as_uint(sA[(m0 + 8) * 32 + k0]);
                a[mi][2] = __float_as_uint(sA[m0 * 32 + k1]);
                a[mi][3] = __float_as_uint(sA[(m0 + 8) * 32 + k1]);
            }
            uint32_t b[4][2];
#pragma unroll
            for (int ni = 0; ni < 4; ni++) {
                int n0 = wn + ni * 8 + gr;
                int nsw = n0 ^ (tg << 3);
                b[ni][0] = __float_as_uint(sB[(kk + tg) * 128 + nsw]);
                b[ni][1] = __float_as_uint(sB[(kk + tg + 4) * 128 + nsw]);
            }
#pragma unroll
            for (int mi = 0; mi < 4; mi++)
#pragma unroll
                for (int ni = 0; ni < 4; ni++)
                    mma_tf32(acc[mi][ni], a[mi], b[ni]);
        }

        buf++; if (buf >= 3) buf = 0;
    }

    // epilogue
#pragma unroll
    for (int mi = 0; mi < 4; mi++) {
        int row0 = bm + wm + mi * 16 + gr;
        int row1 = row0 + 8;
#pragma unroll
        for (int ni = 0; ni < 4; ni++) {
            int col = wn + ni * 8 + 2 * tg;
            float2 b2 = *(const float2*)(bias + col);
            float v0 = acc[mi][ni][0] + b2.x;
            float v1 = acc[mi][ni][1] + b2.y;
            float v2 = acc[mi][ni][2] + b2.x;
            float v3 = acc[mi][ni][3] + b2.y;
            if (RELU) {
                v0 = fmaxf(v0, 0.f); v1 = fmaxf(v1, 0.f);
                v2 = fmaxf(v2, 0.f); v3 = fmaxf(v3, 0.f);
            }
            if (CVT) {
                v0 = tf32rn(v0); v1 = tf32rn(v1);
                v2 = tf32rn(v2); v3 = tf32rn(v3);
            }
            float2 o0 = {v0, v1}, o1 = {v2, v3};
            *(float2*)(C + (size_t)row0 * N + bn + col) = o0;
            *(float2*)(C + (size_t)row1 * N + bn + col) = o1;
        }
    }
}

// ---------------- 5) combine ------------------------
__global__ void combine_kernel(float* __restrict__ out) {
    int t = blockIdx.x;
    int i0 = 2 * t, i1 = 2 * t + 1;
    int e0 = g_item_e[i0], e1 = g_item_e[i1];
    int p0 = g_item_pos[i0], p1 = g_item_pos[i1];
    float w0 = (p0 < CAP) ? g_item_w[i0] : 0.f;
    float w1 = (p1 < CAP) ? g_item_w[i1] : 0.f;
    if (p0 >= CAP) p0 = CAP - 1;
    if (p1 >= CAP) p1 = CAP - 1;
    const float4* s0 = (const float4*)(g_oute + ((size_t)e0 * CAP + p0) * DM);
    const float4* s1 = (const float4*)(g_oute + ((size_t)e1 * CAP + p1) * DM);
    float4* dst = (float4*)(out + (size_t)t * DM);
    for (int j = threadIdx.x; j < DM/4; j += blockDim.x) {
        float4 a = s0[j], b = s1[j];
        float4 r;
        r.x = w0 * a.x + w1 * b.x;
        r.y = w0 * a.y + w1 * b.y;
        r.z = w0 * a.z + w1 * b.z;
        r.w = w0 * a.w + w1 * b.w;
        dst[j] = r;
    }
}

// ---------------- launcher --------------------------
extern "C" void kernel_launch(void* const* d_in, const int* in_sizes, int n_in,
                              void* d_out, int out_size) {
    const float* x  = (const float*)d_in[0];
    const float* gw = (const float*)d_in[1];
    const float* w1 = (const float*)d_in[2];
    const float* b1 = (const float*)d_in[3];
    const float* w2 = (const float*)d_in[4];
    const float* b2 = (const float*)d_in[5];
    float* out = (float*)d_out;

    void *pbuf, *ph, *poute, *pw1r, *pw2r;
    cudaGetSymbolAddress(&pbuf,  g_buf);
    cudaGetSymbolAddress(&ph,    g_h);
    cudaGetSymbolAddress(&poute, g_oute);
    cudaGetSymbolAddress(&pw1r,  g_w1r);
    cudaGetSymbolAddress(&pw2r,  g_w2r);

    cudaFuncSetAttribute(moe_gemm<true,  true >, cudaFuncAttributeMaxDynamicSharedMemorySize, GSMEM);
    cudaFuncSetAttribute(moe_gemm<false, false>, cudaFuncAttributeMaxDynamicSharedMemorySize, GSMEM);

    gating_kernel<<<T_TOKENS, 128>>>(x, gw);
    position_kernel<<<1, 256>>>();
    dispatch_kernel<<<NITEMS, 128>>>(x);

    // pre-round weights to tf32 (same layout, removes all in-loop cvt)
    size_t wn4 = (size_t)NEXP * DM * DH / 4;
    weight_cvt_kernel<<<2048, 256>>>(w1, (float*)pw1r, wn4);
    weight_cvt_kernel<<<2048, 256>>>(w2, (float*)pw2r, wn4);

    // h = relu(buf @ w1 + b1): N=DH, K=DM
    moe_gemm<true,  true ><<<dim3(DH/128, CAP/128, NEXP), 256, GSMEM>>>(
        (const float*)pbuf, (const float*)pw1r, b1, (float*)ph, DH, DM);
    // oute = h @ w2 + b2: N=DM, K=DH
    moe_gemm<false, false><<<dim3(DM/128, CAP/128, NEXP), 256, GSMEM>>>(
        (const float*)ph, (const float*)pw2r, b2, (float*)poute, DM, DH);

    combine_kernel<<<T_TOKENS, 128>>>(out);
}